// round 14
// baseline (speedup 1.0000x reference)
#include <cuda_runtime.h>
#include <cuda_bf16.h>
#include <math.h>

// Problem constants: B=32, T=512, D=H=512, L=2
// Inputs (metadata order): x, Wr, br, Wu, bu, Wo, bo
// Output: (L, B, H) float32 = 32768 elements.

// ---------------- device scratch (no cudaMalloc allowed) ----------------
__device__ float    g_XP[(size_t)16384 * 1536];   // x-projections [m=t*32+b][n=g*512+j]
__device__ float    g_Hseq[(size_t)16384 * 512];  // layer-0 hidden sequence
// seqlock exchange buffers: (value, tag) pairs, [b][j] -> ((b*512+j)*2)
__device__ float    g_hbuf[32 * 512 * 2];
__device__ float    g_hr[32 * 512 * 2];

// bf16-split scratch for tensor-core xproj
__device__ __nv_bfloat16 g_Ah[(size_t)16384 * 512];
__device__ __nv_bfloat16 g_Al[(size_t)16384 * 512];
__device__ __nv_bfloat16 g_Wh[(size_t)3 * 512 * 512];
__device__ __nv_bfloat16 g_Wl[(size_t)3 * 512 * 512];

// ============================================================================
// fp32 -> (bf16 hi, bf16 lo) split helpers
// ============================================================================
__device__ __forceinline__ void split_bf16(float v, __nv_bfloat16& hi, __nv_bfloat16& lo) {
    hi = __float2bfloat16(v);
    lo = __float2bfloat16(v - __bfloat162float(hi));
}

__device__ __forceinline__ void pack_split(float x0, float x1, unsigned& hi, unsigned& lo) {
    __nv_bfloat16 h0, h1, l0, l1;
    split_bf16(x0, h0, l0);
    split_bf16(x1, h1, l1);
    hi = ((unsigned)__bfloat16_as_ushort(h1) << 16) | (unsigned)__bfloat16_as_ushort(h0);
    lo = ((unsigned)__bfloat16_as_ushort(l1) << 16) | (unsigned)__bfloat16_as_ushort(l0);
}

// A matrix conv: 16384 x 512. amode 0: from x[b][t][k] (m=t*32+b). amode 1: from g_Hseq.
// For amode 0 (launch start), blocks 0..63 also zero the seqlock tag buffers.
__global__ __launch_bounds__(256) void convA_kernel(const float* __restrict__ x, int amode) {
    if (amode == 0 && blockIdx.x < 64) {
        int base = (int)blockIdx.x * 1024 + threadIdx.x * 4;
        float4 z = make_float4(0.f, 0.f, 0.f, 0.f);
        if (blockIdx.x < 32) *(float4*)(g_hbuf + base) = z;
        else                 *(float4*)(g_hr + (base - 32768)) = z;
    }
    size_t idx = ((size_t)blockIdx.x * 256 + threadIdx.x) * 4;
    int m = (int)(idx >> 9);
    int k = (int)(idx & 511);
    const float* src = amode ? (g_Hseq + idx)
                             : (x + ((size_t)(m & 31) * 512 + (m >> 5)) * 512 + k);
    float4 v = *(const float4*)src;
    __nv_bfloat16 h0, h1, h2, h3, l0, l1, l2, l3;
    split_bf16(v.x, h0, l0); split_bf16(v.y, h1, l1);
    split_bf16(v.z, h2, l2); split_bf16(v.w, h3, l3);
    ((__nv_bfloat162*)(g_Ah + idx))[0] = __nv_bfloat162(h0, h1);
    ((__nv_bfloat162*)(g_Ah + idx))[1] = __nv_bfloat162(h2, h3);
    ((__nv_bfloat162*)(g_Al + idx))[0] = __nv_bfloat162(l0, l1);
    ((__nv_bfloat162*)(g_Al + idx))[1] = __nv_bfloat162(l2, l3);
}

// W x-halves: g (0=u,1=r,2=o) x 512 j x 512 k  (source row stride 1024)
__global__ __launch_bounds__(256) void convW_kernel(
    const float* __restrict__ Wr, const float* __restrict__ Wu, const float* __restrict__ Wo) {
    size_t idx = ((size_t)blockIdx.x * 256 + threadIdx.x) * 4;
    int g = (int)(idx >> 18);
    int r = (int)(idx & 262143);
    int j = r >> 9, k = r & 511;
    const float* W = (g == 0) ? Wu : (g == 1) ? Wr : Wo;
    float4 v = *(const float4*)(W + (size_t)j * 1024 + k);
    __nv_bfloat16 h0, h1, h2, h3, l0, l1, l2, l3;
    split_bf16(v.x, h0, l0); split_bf16(v.y, h1, l1);
    split_bf16(v.z, h2, l2); split_bf16(v.w, h3, l3);
    ((__nv_bfloat162*)(g_Wh + idx))[0] = __nv_bfloat162(h0, h1);
    ((__nv_bfloat162*)(g_Wh + idx))[1] = __nv_bfloat162(h2, h3);
    ((__nv_bfloat162*)(g_Wl + idx))[0] = __nv_bfloat162(l0, l1);
    ((__nv_bfloat162*)(g_Wl + idx))[1] = __nv_bfloat162(l2, l3);
}

// ============================================================================
// mma.sync m16n8k16 bf16 (row.col, fp32 accum) + ldmatrix
// ============================================================================
__device__ __forceinline__ void mma_bf16(float* c, const unsigned* a, const unsigned* b) {
    asm volatile("mma.sync.aligned.m16n8k16.row.col.f32.bf16.bf16.f32 "
                 "{%0,%1,%2,%3}, {%4,%5,%6,%7}, {%8,%9}, {%0,%1,%2,%3};"
                 : "+f"(c[0]), "+f"(c[1]), "+f"(c[2]), "+f"(c[3])
                 : "r"(a[0]), "r"(a[1]), "r"(a[2]), "r"(a[3]), "r"(b[0]), "r"(b[1]));
}

__device__ __forceinline__ void ldsm_x4(unsigned& r0, unsigned& r1, unsigned& r2, unsigned& r3,
                                        const __nv_bfloat16* p) {
    unsigned a = (unsigned)__cvta_generic_to_shared(p);
    asm volatile("ldmatrix.sync.aligned.m8n8.x4.shared.b16 {%0,%1,%2,%3}, [%4];"
                 : "=r"(r0), "=r"(r1), "=r"(r2), "=r"(r3) : "r"(a));
}

// ============================================================================
// Tensor-core xproj (unchanged, ~265us/layer)
// ============================================================================
#define SM_PITCH 40

__global__ __launch_bounds__(256) void xproj_mma_kernel(
    const float* __restrict__ br, const float* __restrict__ bu, const float* __restrict__ bo) {
    __shared__ __nv_bfloat16 Ah_s[128][SM_PITCH];
    __shared__ __nv_bfloat16 Al_s[128][SM_PITCH];
    __shared__ __nv_bfloat16 Wh_s[64][SM_PITCH];
    __shared__ __nv_bfloat16 Wl_s[64][SM_PITCH];

    int tid = threadIdx.x;
    int m0 = blockIdx.x * 128;
    int n0 = blockIdx.y * 64;
    int g = n0 >> 9, j0 = n0 & 511;
    const float* bv = (g == 0) ? bu : (g == 1) ? br : bo;

    int w = tid >> 5, lane = tid & 31;
    int wm = w >> 1, wn = w & 1;

    float acc[2][4][4];
#pragma unroll
    for (int mf = 0; mf < 2; mf++)
#pragma unroll
        for (int nf = 0; nf < 4; nf++)
#pragma unroll
            for (int i = 0; i < 4; i++) acc[mf][nf][i] = 0.f;

    for (int k0 = 0; k0 < 512; k0 += 32) {
#pragma unroll
        for (int q = 0; q < 2; q++) {
            int u = q * 256 + tid;
            int row = u >> 2, c8 = (u & 3) * 8;
            size_t go = (size_t)(m0 + row) * 512 + k0 + c8;
            *(uint4*)&Ah_s[row][c8] = *(const uint4*)(g_Ah + go);
            *(uint4*)&Al_s[row][c8] = *(const uint4*)(g_Al + go);
        }
        {
            int row = tid >> 2, c8 = (tid & 3) * 8;
            size_t go = ((size_t)g * 512 + j0 + row) * 512 + k0 + c8;
            *(uint4*)&Wh_s[row][c8] = *(const uint4*)(g_Wh + go);
            *(uint4*)&Wl_s[row][c8] = *(const uint4*)(g_Wl + go);
        }
        __syncthreads();

#pragma unroll
        for (int k16 = 0; k16 < 32; k16 += 16) {
            unsigned ah[2][4], al[2][4], bh[4][2], bl[4][2];
            int arow = wm * 32 + (lane & 15);
            int acol = k16 + (lane >> 4) * 8;
#pragma unroll
            for (int mf = 0; mf < 2; mf++) {
                ldsm_x4(ah[mf][0], ah[mf][1], ah[mf][2], ah[mf][3], &Ah_s[arow + mf * 16][acol]);
                ldsm_x4(al[mf][0], al[mf][1], al[mf][2], al[mf][3], &Al_s[arow + mf * 16][acol]);
            }
            int brow_ = ((lane & 16) >> 1) + (lane & 7);
            int bcol = k16 + ((lane >> 3) & 1) * 8;
#pragma unroll
            for (int nh = 0; nh < 2; nh++) {
                int rr = wn * 32 + nh * 16 + brow_;
                ldsm_x4(bh[nh * 2][0], bh[nh * 2][1], bh[nh * 2 + 1][0], bh[nh * 2 + 1][1],
                        &Wh_s[rr][bcol]);
                ldsm_x4(bl[nh * 2][0], bl[nh * 2][1], bl[nh * 2 + 1][0], bl[nh * 2 + 1][1],
                        &Wl_s[rr][bcol]);
            }
#pragma unroll
            for (int mf = 0; mf < 2; mf++)
#pragma unroll
                for (int nf = 0; nf < 4; nf++) {
                    mma_bf16(acc[mf][nf], ah[mf], bh[nf]);
                    mma_bf16(acc[mf][nf], ah[mf], bl[nf]);
                    mma_bf16(acc[mf][nf], al[mf], bh[nf]);
                }
        }
        __syncthreads();
    }

#pragma unroll
    for (int nf = 0; nf < 4; nf++) {
        int jc = j0 + wn * 32 + nf * 8 + (lane & 3) * 2;
        float b0 = __ldg(bv + jc), b1 = __ldg(bv + jc + 1);
        int ncol = n0 + wn * 32 + nf * 8 + (lane & 3) * 2;
#pragma unroll
        for (int mf = 0; mf < 2; mf++) {
            int r0 = m0 + wm * 32 + mf * 16 + (lane >> 2);
            float2 v0 = make_float2(acc[mf][nf][0] + b0, acc[mf][nf][1] + b1);
            float2 v1 = make_float2(acc[mf][nf][2] + b0, acc[mf][nf][3] + b1);
            *(float2*)(g_XP + (size_t)r0 * 1536 + ncol) = v0;
            *(float2*)(g_XP + (size_t)(r0 + 8) * 1536 + ncol) = v1;
        }
    }
}

// ============================================================================
// Persistent scan kernel — seqlock exchange: h and h*r published as atomic
// 8B (value, tag) pairs; consumers spin directly on the data. No flags, no
// fences, no ping-pong. 128 CTAs = 32 col-groups (16 j) x 4 batch-groups.
// ============================================================================

__device__ __forceinline__ float4 ldvol4(const float* p) {
    float4 v;
    asm volatile("ld.volatile.global.v4.f32 {%0,%1,%2,%3}, [%4];"
                 : "=f"(v.x), "=f"(v.y), "=f"(v.z), "=f"(v.w) : "l"(p) : "memory");
    return v;
}

__device__ __forceinline__ void stvol2(float* p, float a, float b) {
    asm volatile("st.volatile.global.v2.f32 [%0], {%1,%2};"
                 :: "l"(p), "f"(a), "f"(b) : "memory");
}

// spin until both embedded tags match; returns the two values
__device__ __forceinline__ float2 wait_pair2(const float* base, unsigned tag) {
    float4 v;
    do { v = ldvol4(base); }
    while (__float_as_uint(v.y) != tag || __float_as_uint(v.w) != tag);
    return make_float2(v.x, v.z);
}

__global__ __launch_bounds__(512, 1) void scan_kernel(
    int layer,
    const float* __restrict__ Wr_l, const float* __restrict__ Wu_l,
    const float* __restrict__ Wo_l,
    float* __restrict__ dout)
{
    __shared__ float redA[16 * 128];   // phase-A split-K partials (r gate)
    __shared__ float redB[16 * 256];   // phase-B partials (u and o gates)

    int tid = threadIdx.x;
    int cg = blockIdx.x >> 2;    // column group: j in [cg*16, cg*16+16)
    int bg = blockIdx.x & 3;     // batch group:  b in [bg*8,  bg*8+8)

    int w = tid >> 5, lane = tid & 31;
    int q = lane & 3;
    int r = lane >> 2;
    int k0 = 32 * w;             // this warp's k-slice of the recurrent half

    // ---- step-invariant weight fragments (bf16-split), registers only ----
    unsigned arh[2][4], arl[2][4], auh[2][4], aul[2][4], aoh[2][4], aol[2][4];
#pragma unroll
    for (int ks = 0; ks < 2; ks++)
#pragma unroll
        for (int i = 0; i < 4; i++) {
            int row = cg * 16 + r + 8 * (i & 1);
            int col = 512 + k0 + 16 * ks + 2 * q + 8 * (i >> 1);
            float2 vr = *(const float2*)(Wr_l + (size_t)row * 1024 + col);
            float2 vu = *(const float2*)(Wu_l + (size_t)row * 1024 + col);
            float2 vo = *(const float2*)(Wo_l + (size_t)row * 1024 + col);
            pack_split(vr.x, vr.y, arh[ks][i], arl[ks][i]);
            pack_split(vu.x, vu.y, auh[ks][i], aul[ks][i]);
            pack_split(vo.x, vo.y, aoh[ks][i], aol[ks][i]);
        }

    // output mapping for tid < 128 (coalesced: jl fastest)
    int jl = tid & 15, bloc = (tid >> 4) & 7;
    int j = cg * 16 + jl;
    int bglob = bg * 8 + bloc;
    unsigned tbase = (unsigned)(layer * 512);

    // publish h0 = 0 with tag tbase+1
    float h_old = 0.f;
    if (tid < 128)
        stvol2(g_hbuf + ((size_t)bglob * 512 + j) * 2, 0.f, __uint_as_float(tbase + 1));

    for (int t = 0; t < 512; t++) {
        unsigned tagH  = tbase + (unsigned)t + 1;   // h(t) tag
        unsigned tagHR = tagH;                      // hr(t) tag (same step)

        // ---- per-thread XP prefetch (independent of exchange) ----
        float xp_u = 0.f, xp_r = 0.f, xp_o = 0.f;
        if (tid < 128) {
            size_t m = (size_t)t * 32 + bglob;
            const float* xp = g_XP + m * 1536 + j;
            xp_u = __ldg(xp);
            xp_r = __ldg(xp + 512);
            xp_o = __ldg(xp + 1024);
        }

        // ---- phase A: spin on h(t) pairs for this warp's k-slice ----
        unsigned bh1[2][2], bl1[2][2];
#pragma unroll
        for (int ks = 0; ks < 2; ks++) {
            const float* hp = g_hbuf + ((size_t)(bg * 8 + r) * 512 + k0 + 16 * ks + 2 * q) * 2;
            float2 v0 = wait_pair2(hp, tagH);
            float2 v1 = wait_pair2(hp + 16, tagH);   // k + 8
            pack_split(v0.x, v0.y, bh1[ks][0], bl1[ks][0]);
            pack_split(v1.x, v1.y, bh1[ks][1], bl1[ks][1]);
        }

        float c1[4] = {0.f, 0.f, 0.f, 0.f};
#pragma unroll
        for (int ks = 0; ks < 2; ks++) {
            mma_bf16(c1, arh[ks], bh1[ks]);
            mma_bf16(c1, arh[ks], bl1[ks]);
            mma_bf16(c1, arl[ks], bh1[ks]);
        }
        // partials: index p = b*16 + jl  (c frag: rows r,r+8 = jl; cols 2q,2q+1 = b)
        {
            float* rp = redA + w * 128;
            rp[(2 * q) * 16 + r]         = c1[0];
            rp[(2 * q + 1) * 16 + r]     = c1[1];
            rp[(2 * q) * 16 + r + 8]     = c1[2];
            rp[(2 * q + 1) * 16 + r + 8] = c1[3];
        }
        __syncthreads();
        if (tid < 128) {
            float s = 0.f;
#pragma unroll
            for (int ww = 0; ww < 16; ww++) s += redA[ww * 128 + tid];
            float rr = 1.f / (1.f + expf(-(s + xp_r)));
            stvol2(g_hr + ((size_t)bglob * 512 + j) * 2, h_old * rr, __uint_as_float(tagHR));
        }

        // ---- phase B: spin on hr(t) pairs; compute o (fresh) + u (retained h) ----
        unsigned bh2[2][2], bl2[2][2];
#pragma unroll
        for (int ks = 0; ks < 2; ks++) {
            const float* hp = g_hr + ((size_t)(bg * 8 + r) * 512 + k0 + 16 * ks + 2 * q) * 2;
            float2 v0 = wait_pair2(hp, tagHR);
            float2 v1 = wait_pair2(hp + 16, tagHR);
            pack_split(v0.x, v0.y, bh2[ks][0], bl2[ks][0]);
            pack_split(v1.x, v1.y, bh2[ks][1], bl2[ks][1]);
        }
        float cu[4] = {0.f, 0.f, 0.f, 0.f};
        float co[4] = {0.f, 0.f, 0.f, 0.f};
#pragma unroll
        for (int ks = 0; ks < 2; ks++) {
            mma_bf16(cu, auh[ks], bh1[ks]);
            mma_bf16(cu, auh[ks], bl1[ks]);
            mma_bf16(cu, aul[ks], bh1[ks]);
            mma_bf16(co, aoh[ks], bh2[ks]);
            mma_bf16(co, aoh[ks], bl2[ks]);
            mma_bf16(co, aol[ks], bh2[ks]);
        }
        {
            float* rp = redB + w * 256;
            rp[(2 * q) * 16 + r]               = cu[0];
            rp[(2 * q + 1) * 16 + r]           = cu[1];
            rp[(2 * q) * 16 + r + 8]           = cu[2];
            rp[(2 * q + 1) * 16 + r + 8]       = cu[3];
            rp[128 + (2 * q) * 16 + r]         = co[0];
            rp[128 + (2 * q + 1) * 16 + r]     = co[1];
            rp[128 + (2 * q) * 16 + r + 8]     = co[2];
            rp[128 + (2 * q + 1) * 16 + r + 8] = co[3];
        }
        __syncthreads();
        if (tid < 128) {
            float su = 0.f, so = 0.f;
#pragma unroll
            for (int ww = 0; ww < 16; ww++) {
                su += redB[ww * 256 + tid];
                so += redB[ww * 256 + 128 + tid];
            }
            float u  = 1.f / (1.f + expf(-(su + xp_u)));
            float ov = tanhf(so + xp_o);
            float hn = fmaf(u, ov - h_old, h_old);    // h*(1-u) + o*u
            h_old = hn;
            stvol2(g_hbuf + ((size_t)bglob * 512 + j) * 2, hn, __uint_as_float(tagH + 1));
            if (layer == 0) g_Hseq[((size_t)t * 32 + bglob) * 512 + j] = hn;
            if (t == 511) dout[layer * 16384 + bglob * 512 + j] = hn;
        }
    }
}

// ============================================================================
extern "C" void kernel_launch(void* const* d_in, const int* in_sizes, int n_in,
                              void* d_out, int out_size)
{
    (void)in_sizes; (void)n_in; (void)out_size;
    const float* x  = (const float*)d_in[0];
    const float* Wr = (const float*)d_in[1];
    const float* br = (const float*)d_in[2];
    const float* Wu = (const float*)d_in[3];
    const float* bu = (const float*)d_in[4];
    const float* Wo = (const float*)d_in[5];
    const float* bo = (const float*)d_in[6];
    float* out = (float*)d_out;

    for (int l = 0; l < 2; l++) {
        size_t woff = (size_t)l * 512 * 1024;
        convA_kernel<<<8192, 256>>>(x, l);   // l==0: blocks 0..63 reset seqlock tags
        convW_kernel<<<768, 256>>>(Wr + woff, Wu + woff, Wo + woff);
        xproj_mma_kernel<<<dim3(128, 24), 256>>>(br + l * 512, bu + l * 512, bo + l * 512);
        scan_kernel<<<128, 512, 0>>>(l, Wr + woff, Wu + woff, Wo + woff, out);
    }
}

// round 15
// speedup vs baseline: 1.2064x; 1.2064x over previous
#include <cuda_runtime.h>
#include <cuda_bf16.h>
#include <math.h>

// Problem constants: B=32, T=512, D=H=512, L=2
// Inputs (metadata order): x, Wr, br, Wu, bu, Wo, bo
// Output: (L, B, H) float32 = 32768 elements.

// ---------------- device scratch (no cudaMalloc allowed) ----------------
__device__ float    g_XP[(size_t)16384 * 1536];   // x-projections [m=t*32+b][n=g*512+j]
__device__ float    g_Hseq[(size_t)16384 * 512];  // layer-0 hidden sequence
__device__ float    g_hbuf[2][32 * 512];          // ping-pong h, [b][j]
__device__ float    g_hr[32 * 512];               // h*r exchange, [b][j]
// point-to-point flags: [bg][cg], each padded to 128B. Monotonic counters.
__device__ unsigned g_flagH[4 * 32 * 32];
__device__ unsigned g_flagR[4 * 32 * 32];

// bf16-split scratch for tensor-core xproj
__device__ __nv_bfloat16 g_Ah[(size_t)16384 * 512];
__device__ __nv_bfloat16 g_Al[(size_t)16384 * 512];
__device__ __nv_bfloat16 g_Wh[(size_t)3 * 512 * 512];
__device__ __nv_bfloat16 g_Wl[(size_t)3 * 512 * 512];

// ============================================================================
// fp32 -> (bf16 hi, bf16 lo) split helpers
// ============================================================================
__device__ __forceinline__ void split_bf16(float v, __nv_bfloat16& hi, __nv_bfloat16& lo) {
    hi = __float2bfloat16(v);
    lo = __float2bfloat16(v - __bfloat162float(hi));
}

__device__ __forceinline__ void pack_split(float x0, float x1, unsigned& hi, unsigned& lo) {
    __nv_bfloat16 h0, h1, l0, l1;
    split_bf16(x0, h0, l0);
    split_bf16(x1, h1, l1);
    hi = ((unsigned)__bfloat16_as_ushort(h1) << 16) | (unsigned)__bfloat16_as_ushort(h0);
    lo = ((unsigned)__bfloat16_as_ushort(l1) << 16) | (unsigned)__bfloat16_as_ushort(l0);
}

// A matrix conv: 16384 x 512. amode 0: from x[b][t][k] (m=t*32+b). amode 1: from g_Hseq.
// Blocks 0..15 also reset the scan flags (stream-ordered, replay-safe).
__global__ __launch_bounds__(256) void convA_kernel(const float* __restrict__ x, int amode) {
    if (blockIdx.x < 16) {
        int f = blockIdx.x * 256 + threadIdx.x;
        g_flagH[f] = 0u;
        g_flagR[f] = 0u;
    }
    size_t idx = ((size_t)blockIdx.x * 256 + threadIdx.x) * 4;
    int m = (int)(idx >> 9);
    int k = (int)(idx & 511);
    const float* src = amode ? (g_Hseq + idx)
                             : (x + ((size_t)(m & 31) * 512 + (m >> 5)) * 512 + k);
    float4 v = *(const float4*)src;
    __nv_bfloat16 h0, h1, h2, h3, l0, l1, l2, l3;
    split_bf16(v.x, h0, l0); split_bf16(v.y, h1, l1);
    split_bf16(v.z, h2, l2); split_bf16(v.w, h3, l3);
    ((__nv_bfloat162*)(g_Ah + idx))[0] = __nv_bfloat162(h0, h1);
    ((__nv_bfloat162*)(g_Ah + idx))[1] = __nv_bfloat162(h2, h3);
    ((__nv_bfloat162*)(g_Al + idx))[0] = __nv_bfloat162(l0, l1);
    ((__nv_bfloat162*)(g_Al + idx))[1] = __nv_bfloat162(l2, l3);
}

// W x-halves: g (0=u,1=r,2=o) x 512 j x 512 k  (source row stride 1024)
__global__ __launch_bounds__(256) void convW_kernel(
    const float* __restrict__ Wr, const float* __restrict__ Wu, const float* __restrict__ Wo) {
    size_t idx = ((size_t)blockIdx.x * 256 + threadIdx.x) * 4;
    int g = (int)(idx >> 18);
    int r = (int)(idx & 262143);
    int j = r >> 9, k = r & 511;
    const float* W = (g == 0) ? Wu : (g == 1) ? Wr : Wo;
    float4 v = *(const float4*)(W + (size_t)j * 1024 + k);
    __nv_bfloat16 h0, h1, h2, h3, l0, l1, l2, l3;
    split_bf16(v.x, h0, l0); split_bf16(v.y, h1, l1);
    split_bf16(v.z, h2, l2); split_bf16(v.w, h3, l3);
    ((__nv_bfloat162*)(g_Wh + idx))[0] = __nv_bfloat162(h0, h1);
    ((__nv_bfloat162*)(g_Wh + idx))[1] = __nv_bfloat162(h2, h3);
    ((__nv_bfloat162*)(g_Wl + idx))[0] = __nv_bfloat162(l0, l1);
    ((__nv_bfloat162*)(g_Wl + idx))[1] = __nv_bfloat162(l2, l3);
}

// ============================================================================
// mma.sync m16n8k16 bf16 (row.col, fp32 accum) + ldmatrix
// ============================================================================
__device__ __forceinline__ void mma_bf16(float* c, const unsigned* a, const unsigned* b) {
    asm volatile("mma.sync.aligned.m16n8k16.row.col.f32.bf16.bf16.f32 "
                 "{%0,%1,%2,%3}, {%4,%5,%6,%7}, {%8,%9}, {%0,%1,%2,%3};"
                 : "+f"(c[0]), "+f"(c[1]), "+f"(c[2]), "+f"(c[3])
                 : "r"(a[0]), "r"(a[1]), "r"(a[2]), "r"(a[3]), "r"(b[0]), "r"(b[1]));
}

__device__ __forceinline__ void ldsm_x4(unsigned& r0, unsigned& r1, unsigned& r2, unsigned& r3,
                                        const __nv_bfloat16* p) {
    unsigned a = (unsigned)__cvta_generic_to_shared(p);
    asm volatile("ldmatrix.sync.aligned.m8n8.x4.shared.b16 {%0,%1,%2,%3}, [%4];"
                 : "=r"(r0), "=r"(r1), "=r"(r2), "=r"(r3) : "r"(a));
}

// ============================================================================
// Tensor-core xproj (unchanged, ~265us/layer)
// ============================================================================
#define SM_PITCH 40

__global__ __launch_bounds__(256) void xproj_mma_kernel(
    const float* __restrict__ br, const float* __restrict__ bu, const float* __restrict__ bo) {
    __shared__ __nv_bfloat16 Ah_s[128][SM_PITCH];
    __shared__ __nv_bfloat16 Al_s[128][SM_PITCH];
    __shared__ __nv_bfloat16 Wh_s[64][SM_PITCH];
    __shared__ __nv_bfloat16 Wl_s[64][SM_PITCH];

    int tid = threadIdx.x;
    int m0 = blockIdx.x * 128;
    int n0 = blockIdx.y * 64;
    int g = n0 >> 9, j0 = n0 & 511;
    const float* bv = (g == 0) ? bu : (g == 1) ? br : bo;

    int w = tid >> 5, lane = tid & 31;
    int wm = w >> 1, wn = w & 1;

    float acc[2][4][4];
#pragma unroll
    for (int mf = 0; mf < 2; mf++)
#pragma unroll
        for (int nf = 0; nf < 4; nf++)
#pragma unroll
            for (int i = 0; i < 4; i++) acc[mf][nf][i] = 0.f;

    for (int k0 = 0; k0 < 512; k0 += 32) {
#pragma unroll
        for (int q = 0; q < 2; q++) {
            int u = q * 256 + tid;
            int row = u >> 2, c8 = (u & 3) * 8;
            size_t go = (size_t)(m0 + row) * 512 + k0 + c8;
            *(uint4*)&Ah_s[row][c8] = *(const uint4*)(g_Ah + go);
            *(uint4*)&Al_s[row][c8] = *(const uint4*)(g_Al + go);
        }
        {
            int row = tid >> 2, c8 = (tid & 3) * 8;
            size_t go = ((size_t)g * 512 + j0 + row) * 512 + k0 + c8;
            *(uint4*)&Wh_s[row][c8] = *(const uint4*)(g_Wh + go);
            *(uint4*)&Wl_s[row][c8] = *(const uint4*)(g_Wl + go);
        }
        __syncthreads();

#pragma unroll
        for (int k16 = 0; k16 < 32; k16 += 16) {
            unsigned ah[2][4], al[2][4], bh[4][2], bl[4][2];
            int arow = wm * 32 + (lane & 15);
            int acol = k16 + (lane >> 4) * 8;
#pragma unroll
            for (int mf = 0; mf < 2; mf++) {
                ldsm_x4(ah[mf][0], ah[mf][1], ah[mf][2], ah[mf][3], &Ah_s[arow + mf * 16][acol]);
                ldsm_x4(al[mf][0], al[mf][1], al[mf][2], al[mf][3], &Al_s[arow + mf * 16][acol]);
            }
            int brow_ = ((lane & 16) >> 1) + (lane & 7);
            int bcol = k16 + ((lane >> 3) & 1) * 8;
#pragma unroll
            for (int nh = 0; nh < 2; nh++) {
                int rr = wn * 32 + nh * 16 + brow_;
                ldsm_x4(bh[nh * 2][0], bh[nh * 2][1], bh[nh * 2 + 1][0], bh[nh * 2 + 1][1],
                        &Wh_s[rr][bcol]);
                ldsm_x4(bl[nh * 2][0], bl[nh * 2][1], bl[nh * 2 + 1][0], bl[nh * 2 + 1][1],
                        &Wl_s[rr][bcol]);
            }
#pragma unroll
            for (int mf = 0; mf < 2; mf++)
#pragma unroll
                for (int nf = 0; nf < 4; nf++) {
                    mma_bf16(acc[mf][nf], ah[mf], bh[nf]);
                    mma_bf16(acc[mf][nf], ah[mf], bl[nf]);
                    mma_bf16(acc[mf][nf], al[mf], bh[nf]);
                }
        }
        __syncthreads();
    }

#pragma unroll
    for (int nf = 0; nf < 4; nf++) {
        int jc = j0 + wn * 32 + nf * 8 + (lane & 3) * 2;
        float b0 = __ldg(bv + jc), b1 = __ldg(bv + jc + 1);
        int ncol = n0 + wn * 32 + nf * 8 + (lane & 3) * 2;
#pragma unroll
        for (int mf = 0; mf < 2; mf++) {
            int r0 = m0 + wm * 32 + mf * 16 + (lane >> 2);
            float2 v0 = make_float2(acc[mf][nf][0] + b0, acc[mf][nf][1] + b1);
            float2 v1 = make_float2(acc[mf][nf][2] + b0, acc[mf][nf][3] + b1);
            *(float2*)(g_XP + (size_t)r0 * 1536 + ncol) = v0;
            *(float2*)(g_XP + (size_t)(r0 + 8) * 1536 + ncol) = v1;
        }
    }
}

// ============================================================================
// Persistent scan kernel — R12 flag protocol + XP prefetch-ahead (SMEM
// double buffer) + phase-B reorder (u-MMAs overlap the hr wait).
// 128 CTAs = 32 col-groups (16 j) x 4 batch-groups (8 b).
// ============================================================================

__device__ __forceinline__ void wait_flag(const unsigned* f, unsigned target) {
    unsigned v;
    do {
        asm volatile("ld.acquire.gpu.global.u32 %0, [%1];" : "=r"(v) : "l"(f) : "memory");
    } while (v < target);
}

__device__ __forceinline__ void bump_flag(unsigned* f) {
    unsigned old;
    asm volatile("atom.release.gpu.global.add.u32 %0, [%1], 1;"
                 : "=r"(old) : "l"(f) : "memory");
}

__device__ __forceinline__ float2 ldvol2(const float* p) {
    float2 v;
    asm volatile("ld.volatile.global.v2.f32 {%0,%1}, [%2];"
                 : "=f"(v.x), "=f"(v.y) : "l"(p) : "memory");
    return v;
}

__global__ __launch_bounds__(512, 1) void scan_kernel(
    int layer,
    const float* __restrict__ Wr_l, const float* __restrict__ Wu_l,
    const float* __restrict__ Wo_l,
    float* __restrict__ dout)
{
    __shared__ float red[16 * 256];   // split-K partials (A: 128/warp; B: 256/warp)
    __shared__ float xps[2 * 384];    // XP prefetch: [parity][g*128 + tid], g:0=u,1=r,2=o

    int tid = threadIdx.x;
    int cg = blockIdx.x >> 2;    // column group: j in [cg*16, cg*16+16)
    int bg = blockIdx.x & 3;     // batch group:  b in [bg*8,  bg*8+8)

    unsigned* flagH = &g_flagH[bg * 32 * 32];   // + cg*32
    unsigned* flagR = &g_flagR[bg * 32 * 32];

    int w = tid >> 5, lane = tid & 31;
    int q = lane & 3;
    int r = lane >> 2;
    int k0 = 32 * w;             // this warp's k-slice of the recurrent half
    int pcg = 2 * w + (lane & 1);   // producer cg polled by lanes 0/1

    // ---- step-invariant weight fragments (bf16-split), registers only ----
    unsigned arh[2][4], arl[2][4], auh[2][4], aul[2][4], aoh[2][4], aol[2][4];
#pragma unroll
    for (int ks = 0; ks < 2; ks++)
#pragma unroll
        for (int i = 0; i < 4; i++) {
            int row = cg * 16 + r + 8 * (i & 1);
            int col = 512 + k0 + 16 * ks + 2 * q + 8 * (i >> 1);
            float2 vr = *(const float2*)(Wr_l + (size_t)row * 1024 + col);
            float2 vu = *(const float2*)(Wu_l + (size_t)row * 1024 + col);
            float2 vo = *(const float2*)(Wo_l + (size_t)row * 1024 + col);
            pack_split(vr.x, vr.y, arh[ks][i], arl[ks][i]);
            pack_split(vu.x, vu.y, auh[ks][i], aul[ks][i]);
            pack_split(vo.x, vo.y, aoh[ks][i], aol[ks][i]);
        }

    // per-thread (j,b) output mapping for tid < 128
    int jl = tid >> 3, bloc = tid & 7;
    int j = cg * 16 + jl;
    int bglob = bg * 8 + bloc;

    // preload XP for t=0 into parity slot 0
    if (tid < 128) {
        const float* xp = g_XP + ((size_t)0 * 32 + bglob) * 1536 + j;
        xps[0 * 384 + 0 * 128 + tid] = __ldg(xp);
        xps[0 * 384 + 1 * 128 + tid] = __ldg(xp + 512);
        xps[0 * 384 + 2 * 128 + tid] = __ldg(xp + 1024);
    }

    // publish h0 = 0 (flagH -> 1)
    float h_old = 0.f;
    if (tid < 128) g_hbuf[0][bglob * 512 + j] = 0.f;
    __syncthreads();
    if (tid == 0) bump_flag(&flagH[cg * 32]);

    int cur = 0;
    for (int t = 0; t < 512; t++) {
        int par = t & 1;

        // ---- prefetch XP for step t+1 (short-lived regs -> SMEM) ----
        if (tid < 128 && t < 511) {
            const float* xp = g_XP + ((size_t)(t + 1) * 32 + bglob) * 1536 + j;
            float a0 = __ldg(xp);
            float a1 = __ldg(xp + 512);
            float a2 = __ldg(xp + 1024);
            xps[(par ^ 1) * 384 + 0 * 128 + tid] = a0;
            xps[(par ^ 1) * 384 + 1 * 128 + tid] = a1;
            xps[(par ^ 1) * 384 + 2 * 128 + tid] = a2;
        }

        // ---- phase A: wait producers of this warp's h k-slice ----
        if (lane < 2) wait_flag(&flagH[pcg * 32], (unsigned)(t + 1));
        __syncwarp();

        unsigned bh1[2][2], bl1[2][2];
#pragma unroll
        for (int ks = 0; ks < 2; ks++) {
            const float* hp = &g_hbuf[cur][(bg * 8 + r) * 512 + k0 + 16 * ks + 2 * q];
            float2 v0 = ldvol2(hp);
            float2 v1 = ldvol2(hp + 8);
            pack_split(v0.x, v0.y, bh1[ks][0], bl1[ks][0]);
            pack_split(v1.x, v1.y, bh1[ks][1], bl1[ks][1]);
        }

        float c1[4] = {0.f, 0.f, 0.f, 0.f};
#pragma unroll
        for (int ks = 0; ks < 2; ks++) {
            mma_bf16(c1, arh[ks], bh1[ks]);
            mma_bf16(c1, arh[ks], bl1[ks]);
            mma_bf16(c1, arl[ks], bh1[ks]);
        }
        {
            float* rp = red + w * 128 + r * 8 + 2 * q;
            *(float2*)rp = make_float2(c1[0], c1[1]);
            *(float2*)(rp + 64) = make_float2(c1[2], c1[3]);
        }
        __syncthreads();
        if (tid < 128) {
            float s = 0.f;
#pragma unroll
            for (int ww = 0; ww < 16; ww++) s += red[ww * 128 + tid];
            float xp_r = xps[par * 384 + 128 + tid];
            float rr = 1.f / (1.f + expf(-(s + xp_r)));
            g_hr[bglob * 512 + j] = h_old * rr;
        }
        __syncthreads();
        if (tid == 0) bump_flag(&flagR[cg * 32]);

        // ---- phase B: u-MMAs first (retained h frags) — overlap the hr wait ----
        float cu[4] = {0.f, 0.f, 0.f, 0.f};
#pragma unroll
        for (int ks = 0; ks < 2; ks++) {
            mma_bf16(cu, auh[ks], bh1[ks]);
            mma_bf16(cu, auh[ks], bl1[ks]);
            mma_bf16(cu, aul[ks], bh1[ks]);
        }
        {
            float* rp = red + w * 256 + r * 8 + 2 * q;
            *(float2*)rp = make_float2(cu[0], cu[1]);
            *(float2*)(rp + 64) = make_float2(cu[2], cu[3]);
        }

        // now wait for hr producers
        if (lane < 2) wait_flag(&flagR[pcg * 32], (unsigned)(t + 1));
        __syncwarp();

        unsigned bh2[2][2], bl2[2][2];
#pragma unroll
        for (int ks = 0; ks < 2; ks++) {
            const float* hp = &g_hr[(bg * 8 + r) * 512 + k0 + 16 * ks + 2 * q];
            float2 v0 = ldvol2(hp);
            float2 v1 = ldvol2(hp + 8);
            pack_split(v0.x, v0.y, bh2[ks][0], bl2[ks][0]);
            pack_split(v1.x, v1.y, bh2[ks][1], bl2[ks][1]);
        }
        float co[4] = {0.f, 0.f, 0.f, 0.f};
#pragma unroll
        for (int ks = 0; ks < 2; ks++) {
            mma_bf16(co, aoh[ks], bh2[ks]);
            mma_bf16(co, aoh[ks], bl2[ks]);
            mma_bf16(co, aol[ks], bh2[ks]);
        }
        {
            float* rp = red + w * 256 + r * 8 + 2 * q;
            *(float2*)(rp + 128) = make_float2(co[0], co[1]);
            *(float2*)(rp + 192) = make_float2(co[2], co[3]);
        }
        __syncthreads();
        if (tid < 128) {
            float su = 0.f, so = 0.f;
#pragma unroll
            for (int ww = 0; ww < 16; ww++) {
                su += red[ww * 256 + tid];
                so += red[ww * 256 + 128 + tid];
            }
            float xp_u = xps[par * 384 + tid];
            float xp_o = xps[par * 384 + 256 + tid];
            float u  = 1.f / (1.f + expf(-(su + xp_u)));
            float ov = tanhf(so + xp_o);
            float hn = fmaf(u, ov - h_old, h_old);    // h*(1-u) + o*u
            h_old = hn;
            g_hbuf[cur ^ 1][bglob * 512 + j] = hn;
            if (layer == 0) g_Hseq[((size_t)t * 32 + bglob) * 512 + j] = hn;
            if (t == 511) dout[layer * 16384 + bglob * 512 + j] = hn;
        }
        __syncthreads();
        if (tid == 0) bump_flag(&flagH[cg * 32]);
        cur ^= 1;
    }
}

// ============================================================================
extern "C" void kernel_launch(void* const* d_in, const int* in_sizes, int n_in,
                              void* d_out, int out_size)
{
    (void)in_sizes; (void)n_in; (void)out_size;
    const float* x  = (const float*)d_in[0];
    const float* Wr = (const float*)d_in[1];
    const float* br = (const float*)d_in[2];
    const float* Wu = (const float*)d_in[3];
    const float* bu = (const float*)d_in[4];
    const float* Wo = (const float*)d_in[5];
    const float* bo = (const float*)d_in[6];
    float* out = (float*)d_out;

    for (int l = 0; l < 2; l++) {
        size_t woff = (size_t)l * 512 * 1024;
        convA_kernel<<<8192, 256>>>(x, l);   // blocks 0..15 also reset flags
        convW_kernel<<<768, 256>>>(Wr + woff, Wu + woff, Wo + woff);
        xproj_mma_kernel<<<dim3(128, 24), 256>>>(br + l * 512, bu + l * 512, bo + l * 512);
        scan_kernel<<<128, 512, 0>>>(l, Wr + woff, Wu + woff, Wo + woff, out);
    }
}

// round 16
// speedup vs baseline: 1.2283x; 1.0181x over previous
#include <cuda_runtime.h>
#include <cuda_bf16.h>
#include <math.h>

// Problem constants: B=32, T=512, D=H=512, L=2
// Inputs (metadata order): x, Wr, br, Wu, bu, Wo, bo
// Output: (L, B, H) float32 = 32768 elements.

// ---------------- device scratch (no cudaMalloc allowed) ----------------
__device__ float    g_XP[(size_t)16384 * 1536];   // x-projections [m=t*32+b][n=g*512+j]
__device__ float    g_hbuf[2][32 * 512];          // ping-pong h, [b][j]
__device__ float    g_hr[32 * 512];               // h*r exchange, [b][j]
// point-to-point flags: [bg][cg], each padded to 128B. Monotonic counters.
__device__ unsigned g_flagH[4 * 32 * 32];
__device__ unsigned g_flagR[4 * 32 * 32];

// bf16-split scratch for tensor-core xproj (layer-1 A written by layer-0 scan)
__device__ __nv_bfloat16 g_Ah[(size_t)16384 * 512];
__device__ __nv_bfloat16 g_Al[(size_t)16384 * 512];
__device__ __nv_bfloat16 g_Wh[(size_t)3 * 512 * 512];
__device__ __nv_bfloat16 g_Wl[(size_t)3 * 512 * 512];

// ============================================================================
// fp32 -> (bf16 hi, bf16 lo) split helpers
// ============================================================================
__device__ __forceinline__ void split_bf16(float v, __nv_bfloat16& hi, __nv_bfloat16& lo) {
    hi = __float2bfloat16(v);
    lo = __float2bfloat16(v - __bfloat162float(hi));
}

__device__ __forceinline__ void pack_split(float x0, float x1, unsigned& hi, unsigned& lo) {
    __nv_bfloat16 h0, h1, l0, l1;
    split_bf16(x0, h0, l0);
    split_bf16(x1, h1, l1);
    hi = ((unsigned)__bfloat16_as_ushort(h1) << 16) | (unsigned)__bfloat16_as_ushort(h0);
    lo = ((unsigned)__bfloat16_as_ushort(l1) << 16) | (unsigned)__bfloat16_as_ushort(l0);
}

// A matrix conv (layer 0 only): 16384 x 512 from x[b][t][k] (m = t*32+b).
// Blocks 0..15 also reset the scan flags (stream-ordered, replay-safe).
__global__ __launch_bounds__(256) void convA_kernel(const float* __restrict__ x) {
    if (blockIdx.x < 16) {
        int f = blockIdx.x * 256 + threadIdx.x;
        g_flagH[f] = 0u;
        g_flagR[f] = 0u;
    }
    size_t idx = ((size_t)blockIdx.x * 256 + threadIdx.x) * 4;
    int m = (int)(idx >> 9);
    int k = (int)(idx & 511);
    const float* src = x + ((size_t)(m & 31) * 512 + (m >> 5)) * 512 + k;
    float4 v = *(const float4*)src;
    __nv_bfloat16 h0, h1, h2, h3, l0, l1, l2, l3;
    split_bf16(v.x, h0, l0); split_bf16(v.y, h1, l1);
    split_bf16(v.z, h2, l2); split_bf16(v.w, h3, l3);
    ((__nv_bfloat162*)(g_Ah + idx))[0] = __nv_bfloat162(h0, h1);
    ((__nv_bfloat162*)(g_Ah + idx))[1] = __nv_bfloat162(h2, h3);
    ((__nv_bfloat162*)(g_Al + idx))[0] = __nv_bfloat162(l0, l1);
    ((__nv_bfloat162*)(g_Al + idx))[1] = __nv_bfloat162(l2, l3);
}

// W x-halves: g (0=u,1=r,2=o) x 512 j x 512 k  (source row stride 1024)
// Blocks 0..15 also reset the scan flags (needed before EACH layer's scan).
__global__ __launch_bounds__(256) void convW_kernel(
    const float* __restrict__ Wr, const float* __restrict__ Wu, const float* __restrict__ Wo) {
    if (blockIdx.x < 16) {
        int f = blockIdx.x * 256 + threadIdx.x;
        g_flagH[f] = 0u;
        g_flagR[f] = 0u;
    }
    size_t idx = ((size_t)blockIdx.x * 256 + threadIdx.x) * 4;
    int g = (int)(idx >> 18);
    int r = (int)(idx & 262143);
    int j = r >> 9, k = r & 511;
    const float* W = (g == 0) ? Wu : (g == 1) ? Wr : Wo;
    float4 v = *(const float4*)(W + (size_t)j * 1024 + k);
    __nv_bfloat16 h0, h1, h2, h3, l0, l1, l2, l3;
    split_bf16(v.x, h0, l0); split_bf16(v.y, h1, l1);
    split_bf16(v.z, h2, l2); split_bf16(v.w, h3, l3);
    ((__nv_bfloat162*)(g_Wh + idx))[0] = __nv_bfloat162(h0, h1);
    ((__nv_bfloat162*)(g_Wh + idx))[1] = __nv_bfloat162(h2, h3);
    ((__nv_bfloat162*)(g_Wl + idx))[0] = __nv_bfloat162(l0, l1);
    ((__nv_bfloat162*)(g_Wl + idx))[1] = __nv_bfloat162(l2, l3);
}

// ============================================================================
// mma.sync m16n8k16 bf16 (row.col, fp32 accum) + ldmatrix
// ============================================================================
__device__ __forceinline__ void mma_bf16(float* c, const unsigned* a, const unsigned* b) {
    asm volatile("mma.sync.aligned.m16n8k16.row.col.f32.bf16.bf16.f32 "
                 "{%0,%1,%2,%3}, {%4,%5,%6,%7}, {%8,%9}, {%0,%1,%2,%3};"
                 : "+f"(c[0]), "+f"(c[1]), "+f"(c[2]), "+f"(c[3])
                 : "r"(a[0]), "r"(a[1]), "r"(a[2]), "r"(a[3]), "r"(b[0]), "r"(b[1]));
}

__device__ __forceinline__ void ldsm_x4(unsigned& r0, unsigned& r1, unsigned& r2, unsigned& r3,
                                        const __nv_bfloat16* p) {
    unsigned a = (unsigned)__cvta_generic_to_shared(p);
    asm volatile("ldmatrix.sync.aligned.m8n8.x4.shared.b16 {%0,%1,%2,%3}, [%4];"
                 : "=r"(r0), "=r"(r1), "=r"(r2), "=r"(r3) : "r"(a));
}

// ============================================================================
// Tensor-core xproj: BM=128, BN=128, BK=32, 256 threads = 8 warps (4m x 2n),
// warp tile 32x64. bf16-split AhWh + AhWl + AlWh.
// ============================================================================
#define SM_PITCH 40

__global__ __launch_bounds__(256, 2) void xproj_mma_kernel(
    const float* __restrict__ br, const float* __restrict__ bu, const float* __restrict__ bo) {
    __shared__ __nv_bfloat16 Ah_s[128][SM_PITCH];
    __shared__ __nv_bfloat16 Al_s[128][SM_PITCH];
    __shared__ __nv_bfloat16 Wh_s[128][SM_PITCH];
    __shared__ __nv_bfloat16 Wl_s[128][SM_PITCH];

    int tid = threadIdx.x;
    int m0 = blockIdx.x * 128;
    int n0 = blockIdx.y * 128;
    int g = n0 >> 9, j0 = n0 & 511;
    const float* bv = (g == 0) ? bu : (g == 1) ? br : bo;

    int w = tid >> 5, lane = tid & 31;
    int wm = w >> 1, wn = w & 1;

    float acc[2][8][4];
#pragma unroll
    for (int mf = 0; mf < 2; mf++)
#pragma unroll
        for (int nf = 0; nf < 8; nf++)
#pragma unroll
            for (int i = 0; i < 4; i++) acc[mf][nf][i] = 0.f;

    for (int k0 = 0; k0 < 512; k0 += 32) {
#pragma unroll
        for (int q = 0; q < 2; q++) {
            int u = q * 256 + tid;
            int row = u >> 2, c8 = (u & 3) * 8;
            size_t go = (size_t)(m0 + row) * 512 + k0 + c8;
            *(uint4*)&Ah_s[row][c8] = *(const uint4*)(g_Ah + go);
            *(uint4*)&Al_s[row][c8] = *(const uint4*)(g_Al + go);
            size_t gw = ((size_t)g * 512 + j0 + row) * 512 + k0 + c8;
            *(uint4*)&Wh_s[row][c8] = *(const uint4*)(g_Wh + gw);
            *(uint4*)&Wl_s[row][c8] = *(const uint4*)(g_Wl + gw);
        }
        __syncthreads();

#pragma unroll
        for (int k16 = 0; k16 < 32; k16 += 16) {
            unsigned ah[2][4], al[2][4], bh[8][2], bl[8][2];
            int arow = wm * 32 + (lane & 15);
            int acol = k16 + (lane >> 4) * 8;
#pragma unroll
            for (int mf = 0; mf < 2; mf++) {
                ldsm_x4(ah[mf][0], ah[mf][1], ah[mf][2], ah[mf][3], &Ah_s[arow + mf * 16][acol]);
                ldsm_x4(al[mf][0], al[mf][1], al[mf][2], al[mf][3], &Al_s[arow + mf * 16][acol]);
            }
            int brow_ = ((lane & 16) >> 1) + (lane & 7);
            int bcol = k16 + ((lane >> 3) & 1) * 8;
#pragma unroll
            for (int nh = 0; nh < 4; nh++) {
                int rr = wn * 64 + nh * 16 + brow_;
                ldsm_x4(bh[nh * 2][0], bh[nh * 2][1], bh[nh * 2 + 1][0], bh[nh * 2 + 1][1],
                        &Wh_s[rr][bcol]);
                ldsm_x4(bl[nh * 2][0], bl[nh * 2][1], bl[nh * 2 + 1][0], bl[nh * 2 + 1][1],
                        &Wl_s[rr][bcol]);
            }
#pragma unroll
            for (int mf = 0; mf < 2; mf++)
#pragma unroll
                for (int nf = 0; nf < 8; nf++) {
                    mma_bf16(acc[mf][nf], ah[mf], bh[nf]);
                    mma_bf16(acc[mf][nf], ah[mf], bl[nf]);
                    mma_bf16(acc[mf][nf], al[mf], bh[nf]);
                }
        }
        __syncthreads();
    }

#pragma unroll
    for (int nf = 0; nf < 8; nf++) {
        int jc = j0 + wn * 64 + nf * 8 + (lane & 3) * 2;
        float b0 = __ldg(bv + jc), b1 = __ldg(bv + jc + 1);
        int ncol = n0 + wn * 64 + nf * 8 + (lane & 3) * 2;
#pragma unroll
        for (int mf = 0; mf < 2; mf++) {
            int r0 = m0 + wm * 32 + mf * 16 + (lane >> 2);
            float2 v0 = make_float2(acc[mf][nf][0] + b0, acc[mf][nf][1] + b1);
            float2 v1 = make_float2(acc[mf][nf][2] + b0, acc[mf][nf][3] + b1);
            *(float2*)(g_XP + (size_t)r0 * 1536 + ncol) = v0;
            *(float2*)(g_XP + (size_t)(r0 + 8) * 1536 + ncol) = v1;
        }
    }
}

// ============================================================================
// Persistent scan kernel — R12 flag protocol (best measured). Layer-0 epilogue
// additionally writes the bf16-split of h into g_Ah/g_Al (off the critical
// path, after the flag bump) so layer-1 needs no convA pass.
// 128 CTAs = 32 col-groups (16 j) x 4 batch-groups (8 b).
// ============================================================================

__device__ __forceinline__ void wait_flag(const unsigned* f, unsigned target) {
    unsigned v;
    do {
        asm volatile("ld.acquire.gpu.global.u32 %0, [%1];" : "=r"(v) : "l"(f) : "memory");
    } while (v < target);
}

__device__ __forceinline__ void bump_flag(unsigned* f) {
    unsigned old;
    asm volatile("atom.release.gpu.global.add.u32 %0, [%1], 1;"
                 : "=r"(old) : "l"(f) : "memory");
}

__device__ __forceinline__ float2 ldvol2(const float* p) {
    float2 v;
    asm volatile("ld.volatile.global.v2.f32 {%0,%1}, [%2];"
                 : "=f"(v.x), "=f"(v.y) : "l"(p) : "memory");
    return v;
}

__global__ __launch_bounds__(512, 1) void scan_kernel(
    int layer,
    const float* __restrict__ Wr_l, const float* __restrict__ Wu_l,
    const float* __restrict__ Wo_l,
    float* __restrict__ dout)
{
    __shared__ float red[16 * 256];   // split-K partials

    int tid = threadIdx.x;
    int cg = blockIdx.x >> 2;    // column group: j in [cg*16, cg*16+16)
    int bg = blockIdx.x & 3;     // batch group:  b in [bg*8,  bg*8+8)

    unsigned* flagH = &g_flagH[bg * 32 * 32];   // + cg*32
    unsigned* flagR = &g_flagR[bg * 32 * 32];

    int w = tid >> 5, lane = tid & 31;
    int q = lane & 3;
    int r = lane >> 2;
    int k0 = 32 * w;                 // this warp's k-slice of the recurrent half
    int pcg = 2 * w + (lane & 1);    // producer cg polled by lanes 0/1

    // ---- step-invariant weight fragments (bf16-split), registers only ----
    unsigned arh[2][4], arl[2][4], auh[2][4], aul[2][4], aoh[2][4], aol[2][4];
#pragma unroll
    for (int ks = 0; ks < 2; ks++)
#pragma unroll
        for (int i = 0; i < 4; i++) {
            int row = cg * 16 + r + 8 * (i & 1);
            int col = 512 + k0 + 16 * ks + 2 * q + 8 * (i >> 1);
            float2 vr = *(const float2*)(Wr_l + (size_t)row * 1024 + col);
            float2 vu = *(const float2*)(Wu_l + (size_t)row * 1024 + col);
            float2 vo = *(const float2*)(Wo_l + (size_t)row * 1024 + col);
            pack_split(vr.x, vr.y, arh[ks][i], arl[ks][i]);
            pack_split(vu.x, vu.y, auh[ks][i], aul[ks][i]);
            pack_split(vo.x, vo.y, aoh[ks][i], aol[ks][i]);
        }

    // per-thread (j,b) output mapping for tid < 128
    int jl = tid >> 3, bloc = tid & 7;
    int j = cg * 16 + jl;
    int bglob = bg * 8 + bloc;

    // publish h0 = 0 (flagH -> 1)
    float h_old = 0.f;
    if (tid < 128) g_hbuf[0][bglob * 512 + j] = 0.f;
    __syncthreads();
    if (tid == 0) bump_flag(&flagH[cg * 32]);

    int cur = 0;
    for (int t = 0; t < 512; t++) {
        // ---- per-thread XP prefetch (independent of flags) ----
        float xp_u = 0.f, xp_r = 0.f, xp_o = 0.f;
        if (tid < 128) {
            size_t m = (size_t)t * 32 + bglob;
            const float* xp = g_XP + m * 1536 + j;
            xp_u = __ldg(xp);
            xp_r = __ldg(xp + 512);
            xp_o = __ldg(xp + 1024);
        }

        // ---- phase A: wait producers of this warp's h k-slice ----
        if (lane < 2) wait_flag(&flagH[pcg * 32], (unsigned)(t + 1));
        __syncwarp();

        unsigned bh1[2][2], bl1[2][2];
#pragma unroll
        for (int ks = 0; ks < 2; ks++) {
            const float* hp = &g_hbuf[cur][(bg * 8 + r) * 512 + k0 + 16 * ks + 2 * q];
            float2 v0 = ldvol2(hp);
            float2 v1 = ldvol2(hp + 8);
            pack_split(v0.x, v0.y, bh1[ks][0], bl1[ks][0]);
            pack_split(v1.x, v1.y, bh1[ks][1], bl1[ks][1]);
        }

        float c1[4] = {0.f, 0.f, 0.f, 0.f};
#pragma unroll
        for (int ks = 0; ks < 2; ks++) {
            mma_bf16(c1, arh[ks], bh1[ks]);
            mma_bf16(c1, arh[ks], bl1[ks]);
            mma_bf16(c1, arl[ks], bh1[ks]);
        }
        {
            float* rp = red + w * 128 + r * 8 + 2 * q;
            *(float2*)rp = make_float2(c1[0], c1[1]);
            *(float2*)(rp + 64) = make_float2(c1[2], c1[3]);
        }
        __syncthreads();
        if (tid < 128) {
            float s = 0.f;
#pragma unroll
            for (int ww = 0; ww < 16; ww++) s += red[ww * 128 + tid];
            float rr = 1.f / (1.f + expf(-(s + xp_r)));
            g_hr[bglob * 512 + j] = h_old * rr;
        }
        __syncthreads();
        if (tid == 0) bump_flag(&flagR[cg * 32]);

        // ---- phase B: wait producers of this warp's h*r k-slice ----
        if (lane < 2) wait_flag(&flagR[pcg * 32], (unsigned)(t + 1));
        __syncwarp();

        unsigned bh2[2][2], bl2[2][2];
#pragma unroll
        for (int ks = 0; ks < 2; ks++) {
            const float* hp = &g_hr[(bg * 8 + r) * 512 + k0 + 16 * ks + 2 * q];
            float2 v0 = ldvol2(hp);
            float2 v1 = ldvol2(hp + 8);
            pack_split(v0.x, v0.y, bh2[ks][0], bl2[ks][0]);
            pack_split(v1.x, v1.y, bh2[ks][1], bl2[ks][1]);
        }
        float cu[4] = {0.f, 0.f, 0.f, 0.f};
        float co[4] = {0.f, 0.f, 0.f, 0.f};
#pragma unroll
        for (int ks = 0; ks < 2; ks++) {
            mma_bf16(cu, auh[ks], bh1[ks]);
            mma_bf16(cu, auh[ks], bl1[ks]);
            mma_bf16(cu, aul[ks], bh1[ks]);
            mma_bf16(co, aoh[ks], bh2[ks]);
            mma_bf16(co, aoh[ks], bl2[ks]);
            mma_bf16(co, aol[ks], bh2[ks]);
        }
        {
            float* rp = red + w * 256 + r * 8 + 2 * q;
            *(float2*)rp = make_float2(cu[0], cu[1]);
            *(float2*)(rp + 64) = make_float2(cu[2], cu[3]);
            *(float2*)(rp + 128) = make_float2(co[0], co[1]);
            *(float2*)(rp + 192) = make_float2(co[2], co[3]);
        }
        __syncthreads();
        float hn = 0.f;
        if (tid < 128) {
            float su = 0.f, so = 0.f;
#pragma unroll
            for (int ww = 0; ww < 16; ww++) {
                su += red[ww * 256 + tid];
                so += red[ww * 256 + 128 + tid];
            }
            float u  = 1.f / (1.f + expf(-(su + xp_u)));
            float ov = tanhf(so + xp_o);
            hn = fmaf(u, ov - h_old, h_old);          // h*(1-u) + o*u
            h_old = hn;
            g_hbuf[cur ^ 1][bglob * 512 + j] = hn;
        }
        __syncthreads();
        if (tid == 0) bump_flag(&flagH[cg * 32]);

        // off-critical-path stores (after the bump)
        if (tid < 128) {
            if (layer == 0) {
                __nv_bfloat16 hi, lo;
                split_bf16(hn, hi, lo);
                size_t mi = ((size_t)t * 32 + bglob) * 512 + j;
                g_Ah[mi] = hi;
                g_Al[mi] = lo;
            }
            if (t == 511) dout[layer * 16384 + bglob * 512 + j] = hn;
        }
        cur ^= 1;
    }
}

// ============================================================================
extern "C" void kernel_launch(void* const* d_in, const int* in_sizes, int n_in,
                              void* d_out, int out_size)
{
    (void)in_sizes; (void)n_in; (void)out_size;
    const float* x  = (const float*)d_in[0];
    const float* Wr = (const float*)d_in[1];
    const float* br = (const float*)d_in[2];
    const float* Wu = (const float*)d_in[3];
    const float* bu = (const float*)d_in[4];
    const float* Wo = (const float*)d_in[5];
    const float* bo = (const float*)d_in[6];
    float* out = (float*)d_out;

    // Layer 0
    convA_kernel<<<8192, 256>>>(x);                       // A split + flag reset
    convW_kernel<<<768, 256>>>(Wr, Wu, Wo);               // W split + flag reset
    xproj_mma_kernel<<<dim3(128, 12), 256>>>(br, bu, bo);
    scan_kernel<<<128, 512, 0>>>(0, Wr, Wu, Wo, out);     // also writes g_Ah/g_Al for layer 1

    // Layer 1 (A conversion fused into layer-0 scan)
    size_t woff = (size_t)512 * 1024;
    convW_kernel<<<768, 256>>>(Wr + woff, Wu + woff, Wo + woff);   // + flag reset
    xproj_mma_kernel<<<dim3(128, 12), 256>>>(br + 512, bu + 512, bo + 512);
    scan_kernel<<<128, 512, 0>>>(1, Wr + woff, Wu + woff, Wo + woff, out);
}

// round 17
// speedup vs baseline: 1.2948x; 1.0541x over previous
#include <cuda_runtime.h>
#include <cuda_bf16.h>
#include <math.h>

// Problem constants: B=32, T=512, D=H=512, L=2
// Inputs (metadata order): x, Wr, br, Wu, bu, Wo, bo
// Output: (L, B, H) float32 = 32768 elements.

// ---------------- device scratch (no cudaMalloc allowed) ----------------
__device__ float    g_XP[(size_t)16384 * 1536];   // layer-0 x-projections [m=t*32+b][n=g*512+j]
__device__ float    g_h0[4][32 * 512];            // layer-0 h ring (depth 4), [b][j]
__device__ float    g_h1[4][32 * 512];            // layer-1 h ring (depth 4)
__device__ float    g_hr0[32 * 512];              // layer-0 h*r exchange
__device__ float    g_hr1[32 * 512];              // layer-1 h*r exchange
// point-to-point flags: [bg][cg], each padded to 128B. Monotonic counters.
__device__ unsigned g_flagH0[4 * 32 * 32];
__device__ unsigned g_flagR0[4 * 32 * 32];
__device__ unsigned g_flagH1[4 * 32 * 32];
__device__ unsigned g_flagR1[4 * 32 * 32];

// bf16-split scratch for the layer-0 tensor-core xproj
__device__ __nv_bfloat16 g_Ah[(size_t)16384 * 512];
__device__ __nv_bfloat16 g_Al[(size_t)16384 * 512];
__device__ __nv_bfloat16 g_Wh[(size_t)3 * 512 * 512];
__device__ __nv_bfloat16 g_Wl[(size_t)3 * 512 * 512];

// ============================================================================
// fp32 -> (bf16 hi, bf16 lo) split helpers
// ============================================================================
__device__ __forceinline__ void split_bf16(float v, __nv_bfloat16& hi, __nv_bfloat16& lo) {
    hi = __float2bfloat16(v);
    lo = __float2bfloat16(v - __bfloat162float(hi));
}

__device__ __forceinline__ void pack_split(float x0, float x1, unsigned& hi, unsigned& lo) {
    __nv_bfloat16 h0, h1, l0, l1;
    split_bf16(x0, h0, l0);
    split_bf16(x1, h1, l1);
    hi = ((unsigned)__bfloat16_as_ushort(h1) << 16) | (unsigned)__bfloat16_as_ushort(h0);
    lo = ((unsigned)__bfloat16_as_ushort(l1) << 16) | (unsigned)__bfloat16_as_ushort(l0);
}

// A matrix conv (layer 0 only): 16384 x 512 from x[b][t][k] (m = t*32+b).
// Blocks 0..15 also reset all scan flags (stream-ordered, replay-safe).
__global__ __launch_bounds__(256) void convA_kernel(const float* __restrict__ x) {
    if (blockIdx.x < 16) {
        int f = blockIdx.x * 256 + threadIdx.x;
        g_flagH0[f] = 0u; g_flagR0[f] = 0u;
        g_flagH1[f] = 0u; g_flagR1[f] = 0u;
    }
    size_t idx = ((size_t)blockIdx.x * 256 + threadIdx.x) * 4;
    int m = (int)(idx >> 9);
    int k = (int)(idx & 511);
    const float* src = x + ((size_t)(m & 31) * 512 + (m >> 5)) * 512 + k;
    float4 v = *(const float4*)src;
    __nv_bfloat16 h0, h1, h2, h3, l0, l1, l2, l3;
    split_bf16(v.x, h0, l0); split_bf16(v.y, h1, l1);
    split_bf16(v.z, h2, l2); split_bf16(v.w, h3, l3);
    ((__nv_bfloat162*)(g_Ah + idx))[0] = __nv_bfloat162(h0, h1);
    ((__nv_bfloat162*)(g_Ah + idx))[1] = __nv_bfloat162(h2, h3);
    ((__nv_bfloat162*)(g_Al + idx))[0] = __nv_bfloat162(l0, l1);
    ((__nv_bfloat162*)(g_Al + idx))[1] = __nv_bfloat162(l2, l3);
}

// W x-halves for layer 0: g (0=u,1=r,2=o) x 512 j x 512 k (source row stride 1024)
__global__ __launch_bounds__(256) void convW_kernel(
    const float* __restrict__ Wr, const float* __restrict__ Wu, const float* __restrict__ Wo) {
    size_t idx = ((size_t)blockIdx.x * 256 + threadIdx.x) * 4;
    int g = (int)(idx >> 18);
    int r = (int)(idx & 262143);
    int j = r >> 9, k = r & 511;
    const float* W = (g == 0) ? Wu : (g == 1) ? Wr : Wo;
    float4 v = *(const float4*)(W + (size_t)j * 1024 + k);
    __nv_bfloat16 h0, h1, h2, h3, l0, l1, l2, l3;
    split_bf16(v.x, h0, l0); split_bf16(v.y, h1, l1);
    split_bf16(v.z, h2, l2); split_bf16(v.w, h3, l3);
    ((__nv_bfloat162*)(g_Wh + idx))[0] = __nv_bfloat162(h0, h1);
    ((__nv_bfloat162*)(g_Wh + idx))[1] = __nv_bfloat162(h2, h3);
    ((__nv_bfloat162*)(g_Wl + idx))[0] = __nv_bfloat162(l0, l1);
    ((__nv_bfloat162*)(g_Wl + idx))[1] = __nv_bfloat162(l2, l3);
}

// ============================================================================
// mma.sync m16n8k16 bf16 (row.col, fp32 accum) + ldmatrix
// ============================================================================
__device__ __forceinline__ void mma_bf16(float* c, const unsigned* a, const unsigned* b) {
    asm volatile("mma.sync.aligned.m16n8k16.row.col.f32.bf16.bf16.f32 "
                 "{%0,%1,%2,%3}, {%4,%5,%6,%7}, {%8,%9}, {%0,%1,%2,%3};"
                 : "+f"(c[0]), "+f"(c[1]), "+f"(c[2]), "+f"(c[3])
                 : "r"(a[0]), "r"(a[1]), "r"(a[2]), "r"(a[3]), "r"(b[0]), "r"(b[1]));
}

__device__ __forceinline__ void ldsm_x4(unsigned& r0, unsigned& r1, unsigned& r2, unsigned& r3,
                                        const __nv_bfloat16* p) {
    unsigned a = (unsigned)__cvta_generic_to_shared(p);
    asm volatile("ldmatrix.sync.aligned.m8n8.x4.shared.b16 {%0,%1,%2,%3}, [%4];"
                 : "=r"(r0), "=r"(r1), "=r"(r2), "=r"(r3) : "r"(a));
}

// ============================================================================
// Tensor-core xproj (layer 0): BM=128, BN=128, BK=32 — unchanged from R15
// ============================================================================
#define SM_PITCH 40

__global__ __launch_bounds__(256, 2) void xproj_mma_kernel(
    const float* __restrict__ br, const float* __restrict__ bu, const float* __restrict__ bo) {
    __shared__ __nv_bfloat16 Ah_s[128][SM_PITCH];
    __shared__ __nv_bfloat16 Al_s[128][SM_PITCH];
    __shared__ __nv_bfloat16 Wh_s[128][SM_PITCH];
    __shared__ __nv_bfloat16 Wl_s[128][SM_PITCH];

    int tid = threadIdx.x;
    int m0 = blockIdx.x * 128;
    int n0 = blockIdx.y * 128;
    int g = n0 >> 9, j0 = n0 & 511;
    const float* bv = (g == 0) ? bu : (g == 1) ? br : bo;

    int w = tid >> 5, lane = tid & 31;
    int wm = w >> 1, wn = w & 1;

    float acc[2][8][4];
#pragma unroll
    for (int mf = 0; mf < 2; mf++)
#pragma unroll
        for (int nf = 0; nf < 8; nf++)
#pragma unroll
            for (int i = 0; i < 4; i++) acc[mf][nf][i] = 0.f;

    for (int k0 = 0; k0 < 512; k0 += 32) {
#pragma unroll
        for (int q = 0; q < 2; q++) {
            int u = q * 256 + tid;
            int row = u >> 2, c8 = (u & 3) * 8;
            size_t go = (size_t)(m0 + row) * 512 + k0 + c8;
            *(uint4*)&Ah_s[row][c8] = *(const uint4*)(g_Ah + go);
            *(uint4*)&Al_s[row][c8] = *(const uint4*)(g_Al + go);
            size_t gw = ((size_t)g * 512 + j0 + row) * 512 + k0 + c8;
            *(uint4*)&Wh_s[row][c8] = *(const uint4*)(g_Wh + gw);
            *(uint4*)&Wl_s[row][c8] = *(const uint4*)(g_Wl + gw);
        }
        __syncthreads();

#pragma unroll
        for (int k16 = 0; k16 < 32; k16 += 16) {
            unsigned ah[2][4], al[2][4], bh[8][2], bl[8][2];
            int arow = wm * 32 + (lane & 15);
            int acol = k16 + (lane >> 4) * 8;
#pragma unroll
            for (int mf = 0; mf < 2; mf++) {
                ldsm_x4(ah[mf][0], ah[mf][1], ah[mf][2], ah[mf][3], &Ah_s[arow + mf * 16][acol]);
                ldsm_x4(al[mf][0], al[mf][1], al[mf][2], al[mf][3], &Al_s[arow + mf * 16][acol]);
            }
            int brow_ = ((lane & 16) >> 1) + (lane & 7);
            int bcol = k16 + ((lane >> 3) & 1) * 8;
#pragma unroll
            for (int nh = 0; nh < 4; nh++) {
                int rr = wn * 64 + nh * 16 + brow_;
                ldsm_x4(bh[nh * 2][0], bh[nh * 2][1], bh[nh * 2 + 1][0], bh[nh * 2 + 1][1],
                        &Wh_s[rr][bcol]);
                ldsm_x4(bl[nh * 2][0], bl[nh * 2][1], bl[nh * 2 + 1][0], bl[nh * 2 + 1][1],
                        &Wl_s[rr][bcol]);
            }
#pragma unroll
            for (int mf = 0; mf < 2; mf++)
#pragma unroll
                for (int nf = 0; nf < 8; nf++) {
                    mma_bf16(acc[mf][nf], ah[mf], bh[nf]);
                    mma_bf16(acc[mf][nf], ah[mf], bl[nf]);
                    mma_bf16(acc[mf][nf], al[mf], bh[nf]);
                }
        }
        __syncthreads();
    }

#pragma unroll
    for (int nf = 0; nf < 8; nf++) {
        int jc = j0 + wn * 64 + nf * 8 + (lane & 3) * 2;
        float b0 = __ldg(bv + jc), b1 = __ldg(bv + jc + 1);
        int ncol = n0 + wn * 64 + nf * 8 + (lane & 3) * 2;
#pragma unroll
        for (int mf = 0; mf < 2; mf++) {
            int r0 = m0 + wm * 32 + mf * 16 + (lane >> 2);
            float2 v0 = make_float2(acc[mf][nf][0] + b0, acc[mf][nf][1] + b1);
            float2 v1 = make_float2(acc[mf][nf][2] + b0, acc[mf][nf][3] + b1);
            *(float2*)(g_XP + (size_t)r0 * 1536 + ncol) = v0;
            *(float2*)(g_XP + (size_t)(r0 + 8) * 1536 + ncol) = v1;
        }
    }
}

// ============================================================================
// FUSED persistent scan: layer-0 step t and layer-1 step t-1 per iteration.
// 128 CTAs = 32 col-groups (16 j) x 4 batch-groups (8 b).
// Layer-1 gate pre-acts: Wx1.h0(tau) + Wh1.h1(tau-1) + b1 — Wx1/Wh1 live in
// SMEM bf16-split planes (ldmatrix per step); layer-0 Wh in register frags.
// h0/h1 are 4-deep rings (covers L1's read-one-behind); R12 flag protocol.
// ============================================================================

__device__ __forceinline__ void wait_flag(const unsigned* f, unsigned target) {
    unsigned v;
    do {
        asm volatile("ld.acquire.gpu.global.u32 %0, [%1];" : "=r"(v) : "l"(f) : "memory");
    } while (v < target);
}

__device__ __forceinline__ void bump_flag(unsigned* f) {
    unsigned old;
    asm volatile("atom.release.gpu.global.add.u32 %0, [%1], 1;"
                 : "=r"(old) : "l"(f) : "memory");
}

__device__ __forceinline__ float2 ldvol2(const float* p) {
    float2 v;
    asm volatile("ld.volatile.global.v2.f32 {%0,%1}, [%2];"
                 : "=f"(v.x), "=f"(v.y) : "l"(p) : "memory");
    return v;
}

#define PLANE 8320                  // 16 rows x 520 pitch (bf16)
#define SCAN_SMEM_BYTES (12 * PLANE * 2 + 16 * 256 * 4)   // 199680 + 16384 = 216064

__global__ __launch_bounds__(512, 1) void scan_fused_kernel(
    const float* __restrict__ Wr0, const float* __restrict__ Wu0, const float* __restrict__ Wo0,
    const float* __restrict__ Wr1, const float* __restrict__ Wu1, const float* __restrict__ Wo1,
    const float* __restrict__ br1, const float* __restrict__ bu1, const float* __restrict__ bo1,
    float* __restrict__ dout)
{
    extern __shared__ __nv_bfloat16 sW[];          // 12 planes, then red floats
    float* red = (float*)(sW + 12 * PLANE);        // 16 x 256 floats

    int tid = threadIdx.x;
    int cg = blockIdx.x >> 2;
    int bg = blockIdx.x & 3;

    unsigned* fH0 = &g_flagH0[bg * 32 * 32];
    unsigned* fR0 = &g_flagR0[bg * 32 * 32];
    unsigned* fH1 = &g_flagH1[bg * 32 * 32];
    unsigned* fR1 = &g_flagR1[bg * 32 * 32];

    int w = tid >> 5, lane = tid & 31;
    int q = lane & 3;
    int r = lane >> 2;
    int k0 = 32 * w;
    int pcg = 2 * w + (lane & 1);

    // ---- layer-0 recurrent weight fragments (registers, bf16-split) ----
    unsigned arh[2][4], arl[2][4], auh[2][4], aul[2][4], aoh[2][4], aol[2][4];
#pragma unroll
    for (int ks = 0; ks < 2; ks++)
#pragma unroll
        for (int i = 0; i < 4; i++) {
            int row = cg * 16 + r + 8 * (i & 1);
            int col = 512 + k0 + 16 * ks + 2 * q + 8 * (i >> 1);
            float2 vr = *(const float2*)(Wr0 + (size_t)row * 1024 + col);
            float2 vu = *(const float2*)(Wu0 + (size_t)row * 1024 + col);
            float2 vo = *(const float2*)(Wo0 + (size_t)row * 1024 + col);
            pack_split(vr.x, vr.y, arh[ks][i], arl[ks][i]);
            pack_split(vu.x, vu.y, auh[ks][i], aul[ks][i]);
            pack_split(vo.x, vo.y, aoh[ks][i], aol[ks][i]);
        }

    // ---- layer-1 weights -> SMEM planes (x-half and h-half, hi/lo) ----
    // plane index: gate g(0=r,1=u,2=o)*4 + half(0=x,1=h)*2 + split(0=hi,1=lo)
    {
        const float* srcs[3] = { Wr1, Wu1, Wo1 };
#pragma unroll
        for (int g = 0; g < 3; g++)
#pragma unroll
            for (int half = 0; half < 2; half++) {
                const float* src = srcs[g];
                for (int it = 0; it < 8; it++) {
                    int e = it * 512 + tid;          // 0..4095 float2 slots
                    int row = e >> 8;                // 16 rows x 256 float2
                    int k = (e & 255) * 2;
                    float2 v = *(const float2*)(src + (size_t)(cg * 16 + row) * 1024
                                                + half * 512 + k);
                    unsigned hi, lo;
                    pack_split(v.x, v.y, hi, lo);
                    int pbase = g * 4 + half * 2;
                    *(unsigned*)(sW + (size_t)pbase * PLANE + row * 520 + k) = hi;
                    *(unsigned*)(sW + (size_t)(pbase + 1) * PLANE + row * 520 + k) = lo;
                }
            }
    }

#define LDSA(d, p, ks) ldsm_x4(d[0], d[1], d[2], d[3], \
        sW + (size_t)(p) * PLANE + (lane & 15) * 520 + k0 + 16 * (ks) + 8 * (lane >> 4))

    // per-thread (j,b) output mapping for tid < 128
    int jl = tid >> 3, bloc = tid & 7;
    int j = cg * 16 + jl;
    int bglob = bg * 8 + bloc;

    float b1r_s = 0.f, b1u_s = 0.f, b1o_s = 0.f;
    if (tid < 128) {
        b1r_s = __ldg(br1 + j);
        b1u_s = __ldg(bu1 + j);
        b1o_s = __ldg(bo1 + j);
    }

    // publish h0(-1)=0 (slot 3) and h1(-1)=0 (slot 3)
    float h0_old = 0.f, h1_old = 0.f;
    if (tid < 128) {
        g_h0[3][bglob * 512 + j] = 0.f;
        g_h1[3][bglob * 512 + j] = 0.f;
    }
    __syncthreads();
    if (tid == 0) { bump_flag(&fH0[cg * 32]); bump_flag(&fH1[cg * 32]); }

    for (int t = 0; t <= 512; t++) {
        unsigned bh0p[2][2], bl0p[2][2];   // h0(t-1) frags (x-input of L1 step t-1)

        if (t < 512) {
            // ================= LAYER 0, step t =================
            float xp_u = 0.f, xp_r = 0.f, xp_o = 0.f;
            if (tid < 128) {
                size_t m = (size_t)t * 32 + bglob;
                const float* xp = g_XP + m * 1536 + j;
                xp_u = __ldg(xp);
                xp_r = __ldg(xp + 512);
                xp_o = __ldg(xp + 1024);
            }

            if (lane < 2) wait_flag(&fH0[pcg * 32], (unsigned)(t + 1));
            __syncwarp();

#pragma unroll
            for (int ks = 0; ks < 2; ks++) {
                const float* hp = &g_h0[(t + 3) & 3][(bg * 8 + r) * 512 + k0 + 16 * ks + 2 * q];
                float2 v0 = ldvol2(hp);
                float2 v1 = ldvol2(hp + 8);
                pack_split(v0.x, v0.y, bh0p[ks][0], bl0p[ks][0]);
                pack_split(v1.x, v1.y, bh0p[ks][1], bl0p[ks][1]);
            }

            float c1[4] = {0.f, 0.f, 0.f, 0.f};
#pragma unroll
            for (int ks = 0; ks < 2; ks++) {
                mma_bf16(c1, arh[ks], bh0p[ks]);
                mma_bf16(c1, arh[ks], bl0p[ks]);
                mma_bf16(c1, arl[ks], bh0p[ks]);
            }
            {
                float* rp = red + w * 128 + r * 8 + 2 * q;
                *(float2*)rp = make_float2(c1[0], c1[1]);
                *(float2*)(rp + 64) = make_float2(c1[2], c1[3]);
            }
            __syncthreads();
            if (tid < 128) {
                float s = 0.f;
#pragma unroll
                for (int ww = 0; ww < 16; ww++) s += red[ww * 128 + tid];
                float rr = 1.f / (1.f + expf(-(s + xp_r)));
                g_hr0[bglob * 512 + j] = h0_old * rr;
            }
            __syncthreads();
            if (tid == 0) bump_flag(&fR0[cg * 32]);

            if (lane < 2) wait_flag(&fR0[pcg * 32], (unsigned)(t + 1));
            __syncwarp();

            unsigned bh2[2][2], bl2[2][2];
#pragma unroll
            for (int ks = 0; ks < 2; ks++) {
                const float* hp = &g_hr0[(bg * 8 + r) * 512 + k0 + 16 * ks + 2 * q];
                float2 v0 = ldvol2(hp);
                float2 v1 = ldvol2(hp + 8);
                pack_split(v0.x, v0.y, bh2[ks][0], bl2[ks][0]);
                pack_split(v1.x, v1.y, bh2[ks][1], bl2[ks][1]);
            }
            float cu[4] = {0.f, 0.f, 0.f, 0.f};
            float co[4] = {0.f, 0.f, 0.f, 0.f};
#pragma unroll
            for (int ks = 0; ks < 2; ks++) {
                mma_bf16(cu, auh[ks], bh0p[ks]);
                mma_bf16(cu, auh[ks], bl0p[ks]);
                mma_bf16(cu, aul[ks], bh0p[ks]);
                mma_bf16(co, aoh[ks], bh2[ks]);
                mma_bf16(co, aoh[ks], bl2[ks]);
                mma_bf16(co, aol[ks], bh2[ks]);
            }
            {
                float* rp = red + w * 256 + r * 8 + 2 * q;
                *(float2*)rp = make_float2(cu[0], cu[1]);
                *(float2*)(rp + 64) = make_float2(cu[2], cu[3]);
                *(float2*)(rp + 128) = make_float2(co[0], co[1]);
                *(float2*)(rp + 192) = make_float2(co[2], co[3]);
            }
            __syncthreads();
            if (tid < 128) {
                float su = 0.f, so = 0.f;
#pragma unroll
                for (int ww = 0; ww < 16; ww++) {
                    su += red[ww * 256 + tid];
                    so += red[ww * 256 + 128 + tid];
                }
                float u  = 1.f / (1.f + expf(-(su + xp_u)));
                float ov = tanhf(so + xp_o);
                float hn = fmaf(u, ov - h0_old, h0_old);
                h0_old = hn;
                g_h0[t & 3][bglob * 512 + j] = hn;
                if (t == 511) dout[bglob * 512 + j] = hn;
            }
            __syncthreads();
            if (tid == 0) bump_flag(&fH0[cg * 32]);
        } else {
            // epilogue: load h0(511) frags for the final L1 step
            if (lane < 2) wait_flag(&fH0[pcg * 32], 513u);
            __syncwarp();
#pragma unroll
            for (int ks = 0; ks < 2; ks++) {
                const float* hp = &g_h0[3][(bg * 8 + r) * 512 + k0 + 16 * ks + 2 * q];
                float2 v0 = ldvol2(hp);
                float2 v1 = ldvol2(hp + 8);
                pack_split(v0.x, v0.y, bh0p[ks][0], bl0p[ks][0]);
                pack_split(v1.x, v1.y, bh0p[ks][1], bl0p[ks][1]);
            }
        }

        if (t >= 1) {
            // ================= LAYER 1, step tau = t-1 =================
            int tau = t - 1;
            // bh0p/bl0p hold h0(tau) frags (loaded in L0A above, or epilogue).
            if (lane < 2) wait_flag(&fH1[pcg * 32], (unsigned)(tau + 1));
            __syncwarp();

            unsigned bh1n[2][2], bl1n[2][2];   // h1(tau-1)
#pragma unroll
            for (int ks = 0; ks < 2; ks++) {
                const float* hp = &g_h1[(tau + 3) & 3][(bg * 8 + r) * 512 + k0 + 16 * ks + 2 * q];
                float2 v0 = ldvol2(hp);
                float2 v1 = ldvol2(hp + 8);
                pack_split(v0.x, v0.y, bh1n[ks][0], bl1n[ks][0]);
                pack_split(v1.x, v1.y, bh1n[ks][1], bl1n[ks][1]);
            }

            float c1[4] = {0.f, 0.f, 0.f, 0.f};
#pragma unroll
            for (int ks = 0; ks < 2; ks++) {
                unsigned axh[4], axl[4], ahh[4], ahl[4];
                LDSA(axh, 0, ks); LDSA(axl, 1, ks);
                LDSA(ahh, 2, ks); LDSA(ahl, 3, ks);
                mma_bf16(c1, axh, bh0p[ks]);
                mma_bf16(c1, axh, bl0p[ks]);
                mma_bf16(c1, axl, bh0p[ks]);
                mma_bf16(c1, ahh, bh1n[ks]);
                mma_bf16(c1, ahh, bl1n[ks]);
                mma_bf16(c1, ahl, bh1n[ks]);
            }
            {
                float* rp = red + w * 128 + r * 8 + 2 * q;
                *(float2*)rp = make_float2(c1[0], c1[1]);
                *(float2*)(rp + 64) = make_float2(c1[2], c1[3]);
            }
            __syncthreads();
            if (tid < 128) {
                float s = 0.f;
#pragma unroll
                for (int ww = 0; ww < 16; ww++) s += red[ww * 128 + tid];
                float rr = 1.f / (1.f + expf(-(s + b1r_s)));
                g_hr1[bglob * 512 + j] = h1_old * rr;
            }
            __syncthreads();
            if (tid == 0) bump_flag(&fR1[cg * 32]);

            if (lane < 2) wait_flag(&fR1[pcg * 32], (unsigned)(tau + 1));
            __syncwarp();

            unsigned bhr[2][2], blr[2][2];
#pragma unroll
            for (int ks = 0; ks < 2; ks++) {
                const float* hp = &g_hr1[(bg * 8 + r) * 512 + k0 + 16 * ks + 2 * q];
                float2 v0 = ldvol2(hp);
                float2 v1 = ldvol2(hp + 8);
                pack_split(v0.x, v0.y, bhr[ks][0], blr[ks][0]);
                pack_split(v1.x, v1.y, bhr[ks][1], blr[ks][1]);
            }
            float cu[4] = {0.f, 0.f, 0.f, 0.f};
            float co[4] = {0.f, 0.f, 0.f, 0.f};
#pragma unroll
            for (int ks = 0; ks < 2; ks++) {
                unsigned axh[4], axl[4], ahh[4], ahl[4];
                LDSA(axh, 4, ks); LDSA(axl, 5, ks);
                LDSA(ahh, 6, ks); LDSA(ahl, 7, ks);
                mma_bf16(cu, axh, bh0p[ks]);
                mma_bf16(cu, axh, bl0p[ks]);
                mma_bf16(cu, axl, bh0p[ks]);
                mma_bf16(cu, ahh, bh1n[ks]);
                mma_bf16(cu, ahh, bl1n[ks]);
                mma_bf16(cu, ahl, bh1n[ks]);
                LDSA(axh, 8, ks); LDSA(axl, 9, ks);
                LDSA(ahh, 10, ks); LDSA(ahl, 11, ks);
                mma_bf16(co, axh, bh0p[ks]);
                mma_bf16(co, axh, bl0p[ks]);
                mma_bf16(co, axl, bh0p[ks]);
                mma_bf16(co, ahh, bhr[ks]);
                mma_bf16(co, ahh, blr[ks]);
                mma_bf16(co, ahl, bhr[ks]);
            }
            {
                float* rp = red + w * 256 + r * 8 + 2 * q;
                *(float2*)rp = make_float2(cu[0], cu[1]);
                *(float2*)(rp + 64) = make_float2(cu[2], cu[3]);
                *(float2*)(rp + 128) = make_float2(co[0], co[1]);
                *(float2*)(rp + 192) = make_float2(co[2], co[3]);
            }
            __syncthreads();
            if (tid < 128) {
                float su = 0.f, so = 0.f;
#pragma unroll
                for (int ww = 0; ww < 16; ww++) {
                    su += red[ww * 256 + tid];
                    so += red[ww * 256 + 128 + tid];
                }
                float u  = 1.f / (1.f + expf(-(su + b1u_s)));
                float ov = tanhf(so + b1o_s);
                float hn = fmaf(u, ov - h1_old, h1_old);
                h1_old = hn;
                g_h1[tau & 3][bglob * 512 + j] = hn;
                if (tau == 511) dout[16384 + bglob * 512 + j] = hn;
            }
            __syncthreads();
            if (tid == 0) bump_flag(&fH1[cg * 32]);
        }
    }
#undef LDSA
}

// ============================================================================
extern "C" void kernel_launch(void* const* d_in, const int* in_sizes, int n_in,
                              void* d_out, int out_size)
{
    (void)in_sizes; (void)n_in; (void)out_size;
    const float* x  = (const float*)d_in[0];
    const float* Wr = (const float*)d_in[1];
    const float* br = (const float*)d_in[2];
    const float* Wu = (const float*)d_in[3];
    const float* bu = (const float*)d_in[4];
    const float* Wo = (const float*)d_in[5];
    const float* bo = (const float*)d_in[6];
    float* out = (float*)d_out;

    cudaFuncSetAttribute(scan_fused_kernel,
                         cudaFuncAttributeMaxDynamicSharedMemorySize,
                         SCAN_SMEM_BYTES);

    size_t woff = (size_t)512 * 1024;

    convA_kernel<<<8192, 256>>>(x);                        // A split + all flag resets
    convW_kernel<<<768, 256>>>(Wr, Wu, Wo);                // layer-0 W x-halves
    xproj_mma_kernel<<<dim3(128, 12), 256>>>(br, bu, bo);  // layer-0 XP
    scan_fused_kernel<<<128, 512, SCAN_SMEM_BYTES>>>(
        Wr, Wu, Wo,
        Wr + woff, Wu + woff, Wo + woff,
        br + 512, bu + 512, bo + 512,
        out);
}